// round 13
// baseline (speedup 1.0000x reference)
#include <cuda_runtime.h>
#include <cuda_fp16.h>
#include <cstdint>

// Layout after transpose: per point n, 128 bytes = 16 chunks of 8B.
// Chunk f (f=0..15) = [ x(4f..4f+3) (4 biased int8) | y(4f..4f+3) ].
// Bytes are u = round(clamp(x*127/6, -127, 127)) + 128 (biased).
// One edge endpoint = one 128B row = one LDG.64 across 16 lanes = ONE line.
#define MAX_N 100000
#define E_PAD 240000   // >= E + pipeline lookahead; padded records contribute 0
#define QSCALE (127.0f / 6.0f)
#define DQSCALE (6.0f / 127.0f)
__device__ __align__(128) unsigned char g_buf[(size_t)MAX_N * 128];
// Edge record: {s0*128, s1*128, __float_as_uint(c), 0}
__device__ __align__(16) uint4 g_edges[E_PAD];

// ---------------- helpers ----------------
__device__ __forceinline__ unsigned long long fma2(unsigned long long a,
                                                   unsigned long long b,
                                                   unsigned long long c) {
    unsigned long long r;
    asm("fma.rn.f32x2 %0, %1, %2, %3;" : "=l"(r) : "l"(a), "l"(b), "l"(c));
    return r;
}
__device__ __forceinline__ void upk(unsigned long long v, float& a, float& b) {
    asm("mov.b64 {%0, %1}, %2;" : "=f"(a), "=f"(b) : "l"(v));
}
__device__ __forceinline__ unsigned long long pk(float a, float b) {
    unsigned long long r;
    asm("mov.b64 %0, {%1, %2};" : "=l"(r) : "f"(a), "f"(b));
    return r;
}
__device__ __forceinline__ float sqapx(float x) {
    float r;
    asm("sqrt.approx.f32 %0, %1;" : "=f"(r) : "f"(x));
    return r;
}
__device__ __forceinline__ unsigned prmt(unsigned a, unsigned b, unsigned s) {
    unsigned d;
    asm("prmt.b32 %0, %1, %2, %3;" : "=r"(d) : "r"(a), "r"(b), "r"(s));
    return d;
}
__device__ __forceinline__ __half2 u2h(unsigned w) {
    return *(__half2*)&w;
}
__device__ __forceinline__ unsigned qbyte(float x) {
    float xs = fminf(fmaxf(x * QSCALE, -127.0f), 127.0f);
    return (unsigned)(__float2int_rn(xs) + 128) & 0xffu;
}

// ---------------- Kernel 1: transpose+quantize + edge-record prep ----------
// Blocks [0, tblocks): [64, N] float2 -> biased-int8 chunked g_buf.
// Blocks [tblocks, ...): skeleton (int64 OR int32) + init_len -> padded
// pre-scaled records. Dtype detect per prep block via ballot.
__global__ void __launch_bounds__(256) transpose_kernel(
    const float2* __restrict__ in, const unsigned* __restrict__ skel_raw,
    const float* __restrict__ init_len, float* out, int N, int E, int tblocks) {
    if (blockIdx.x >= tblocks) {
        // ---- prep branch ----
        __shared__ int sh_is64;
        if (threadIdx.x < 32) {
            unsigned v = skel_raw[2 * threadIdx.x + 1] |
                         skel_raw[2 * (threadIdx.x + 32) + 1];
            unsigned b = __ballot_sync(0xffffffffu, v == 0u);
            if (threadIdx.x == 0) sh_is64 = (b == 0xffffffffu);
        }
        __syncthreads();
        int is64 = sh_is64;
        int e = (blockIdx.x - tblocks) * 256 + threadIdx.x;
        if (e == 0) out[0] = 0.0f;
        if (e < E_PAD) {
            uint4 r = make_uint4(0u, 0u, 0u, 0u);
            if (e < E) {
                int s0, s1;
                if (is64) {
                    longlong2 s = ((const longlong2*)skel_raw)[e];
                    s0 = (int)s.x; s1 = (int)s.y;
                } else {
                    int2 s = ((const int2*)skel_raw)[e];
                    s0 = s.x; s1 = s.y;
                }
                r.x = (unsigned)s0 * 128u;
                r.y = (unsigned)s1 * 128u;
                r.z = __float_as_uint(init_len[e]);
            }
            g_edges[e] = r;
        }
        return;
    }

    // ---- transpose branch ----
    __shared__ float2 tile[64][33];
    int n0 = blockIdx.x * 32;
    int tx = threadIdx.x & 31;
    int ty = threadIdx.x >> 5;
    int c = n0 + tx;
    if (c < N) {
#pragma unroll
        for (int i = 0; i < 8; ++i) {
            int b = ty + i * 8;  // frame index 0..63
            tile[b][tx] = __ldcs(&in[(size_t)b * N + c]);
        }
    }
    __syncthreads();
    // 32 points * 16 chunks = 512 items; 256 threads * 2 iters.
#pragma unroll
    for (int k = 0; k < 2; ++k) {
        int l = threadIdx.x + k * 256;
        int f = l & 15;       // chunk (frames 4f..4f+3)
        int cc = l >> 4;      // point within block
        int n = n0 + cc;
        if (n < N) {
            unsigned xw = 0, yw = 0;
#pragma unroll
            for (int i = 0; i < 4; ++i) {
                float2 v = tile[4 * f + i][cc];
                xw |= qbyte(v.x) << (8 * i);
                yw |= qbyte(v.y) << (8 * i);
            }
            *(uint2*)(g_buf + (size_t)n * 128 + f * 8) = make_uint2(xw, yw);
        }
    }
}

// ---------------- Kernel 2: main loss ----------------
// Warp = 2 edges (16 lanes each). Lane covers 4 frames via ONE uint2 chunk
// (8B: 4 x-bytes, 4 y-bytes) per endpoint => 2 gather LDG.64 (1 line each)
// + 1 record LDG.128 per warp-iter. Depth-2 register pipeline. Dequant:
// PRMT bytes into fp16 lanes with exponent 0x64 (value 1024+u); hsub2 of
// two such values is exactly qa-qb (bias cancels); scale by 6/127 before
// squaring (keeps t <= 288, no fp16 overflow). Padded records contribute 0.

struct Rec { unsigned o0, o1; float c; };
struct GatherC { uint2 a, b; };  // 4 regs

__device__ __forceinline__ Rec load_rec(int e) {
    uint4 r = g_edges[e];
    Rec q;
    q.o0 = r.x;
    q.o1 = r.y;
    q.c = __uint_as_float(r.z);
    return q;
}

__device__ __forceinline__ GatherC issue_gather(const char* tb, Rec q) {
    GatherC g;
    g.a = *(const uint2*)(tb + q.o0);
    g.b = *(const uint2*)(tb + q.o1);
    return g;
}

__global__ void __launch_bounds__(256, 6) loss_kernel(
    float* out, int E, float invE) {
    const unsigned long long NEG1 = 0xBF800000BF800000ULL;  // (-1.f, -1.f)
    const unsigned C64 = 0x64646464u;
    const __half2 S = __float2half2_rn(DQSCALE);
    int lane = threadIdx.x & 31;
    int half = lane >> 4;      // which of 2 edges in warp
    int el = lane & 15;        // chunk index within row
    int warp = (blockIdx.x * blockDim.x + threadIdx.x) >> 5;
    int nwarps = (gridDim.x * blockDim.x) >> 5;
    int P = (E + 1) >> 1;
    const char* tb = (const char*)g_buf + (unsigned)el * 8u;

    unsigned long long acc = 0ull;

    // Depth-2 prologue: record+gathers for p; record for p+nw.
    int p = warp;
    Rec qc = load_rec(2 * p + half);
    GatherC gc = issue_gather(tb, qc);
    Rec qn = load_rec(2 * (p + nwarps) + half);

#pragma unroll 2
    for (; p < P; p += nwarps) {
        // Issue next iteration's gathers (record already resident).
        GatherC gn = issue_gather(tb, qn);
        // Load record two iterations ahead (always in-bounds: E_PAD pad).
        Rec qf = load_rec(2 * (p + 2 * nwarps) + half);

        // Compute on current gathers (in flight since previous iteration).
        unsigned long long cc2 = pk(qc.c, qc.c);
        // Dequant via PRMT into 1024+u fp16 lanes; hsub2 cancels the bias.
        __half2 dx01 = __hmul2(__hsub2(u2h(prmt(gc.a.x, C64, 0x4140)),
                                       u2h(prmt(gc.b.x, C64, 0x4140))), S);
        __half2 dx23 = __hmul2(__hsub2(u2h(prmt(gc.a.x, C64, 0x4342)),
                                       u2h(prmt(gc.b.x, C64, 0x4342))), S);
        __half2 dy01 = __hmul2(__hsub2(u2h(prmt(gc.a.y, C64, 0x4140)),
                                       u2h(prmt(gc.b.y, C64, 0x4140))), S);
        __half2 dy23 = __hmul2(__hsub2(u2h(prmt(gc.a.y, C64, 0x4342)),
                                       u2h(prmt(gc.b.y, C64, 0x4342))), S);
        __half2 t01 = __hfma2(dy01, dy01, __hmul2(dx01, dx01));
        __half2 t23 = __hfma2(dy23, dy23, __hmul2(dx23, dx23));
        float2 f01 = __half22float2(t01);
        float2 f23 = __half22float2(t23);
        unsigned long long len0 = pk(sqapx(f01.x), sqapx(f01.y));
        unsigned long long len1 = pk(sqapx(f23.x), sqapx(f23.y));
        unsigned long long d0 = fma2(cc2, NEG1, len0);
        unsigned long long d1 = fma2(cc2, NEG1, len1);
        acc = fma2(d0, d0, acc);
        acc = fma2(d1, d1, acc);

        // Rotate (renamed under unroll).
        qc = qn;
        qn = qf;
        gc = gn;
    }

    float a0, a1;
    upk(acc, a0, a1);
    float s = a0 + a1;
#pragma unroll
    for (int off = 16; off; off >>= 1)
        s += __shfl_down_sync(0xffffffffu, s, off);

    __shared__ float warp_sums[8];
    if (lane == 0) warp_sums[threadIdx.x >> 5] = s;
    __syncthreads();
    if (threadIdx.x < 8) {
        float v = warp_sums[threadIdx.x];
#pragma unroll
        for (int off = 4; off; off >>= 1)
            v += __shfl_down_sync(0xffu, v, off);
        if (threadIdx.x == 0) atomicAdd(out, v * invE);
    }
}

extern "C" void kernel_launch(void* const* d_in, const int* in_sizes, int n_in,
                              void* d_out, int out_size) {
    const float2* pts = (const float2*)d_in[0];
    const void* skel = d_in[1];
    const float* initl = (const float*)d_in[2];
    float* out = (float*)d_out;

    int N = in_sizes[0] / 128;  // B=64 frames, 2 coords
    int E = in_sizes[2];

    int tblocks = (N + 31) / 32;
    int pblocks = (E_PAD + 255) / 256;
    transpose_kernel<<<tblocks + pblocks, 256>>>(
        pts, (const unsigned*)skel, initl, out, N, E, tblocks);
    loss_kernel<<<888, 256>>>(out, E, 1.0f / (float)E);
}

// round 15
// speedup vs baseline: 1.1220x; 1.1220x over previous
#include <cuda_runtime.h>
#include <cuda_fp16.h>
#include <cstdint>

// Layout after transpose: per point n, 256 bytes = 16 chunks of 16B.
// Chunk f (f=0..15) = [ x(4f..4f+3) | y(4f..4f+3) ]  (8 halves).
#define MAX_N 100000
#define E_PAD 260000   // >= 4*(P4 + 2*nwarps)+3 lookahead; pad records => 0
__device__ __align__(256) __half2 g_buf[(size_t)MAX_N * 64];
// Edge record: {s0*256, s1*256, __float_as_uint(c), 0}
__device__ __align__(16) uint4 g_edges[E_PAD];

// ---------------- f32x2 / sqrt.approx helpers ----------------
__device__ __forceinline__ unsigned long long fma2(unsigned long long a,
                                                   unsigned long long b,
                                                   unsigned long long c) {
    unsigned long long r;
    asm("fma.rn.f32x2 %0, %1, %2, %3;" : "=l"(r) : "l"(a), "l"(b), "l"(c));
    return r;
}
__device__ __forceinline__ void upk(unsigned long long v, float& a, float& b) {
    asm("mov.b64 {%0, %1}, %2;" : "=f"(a), "=f"(b) : "l"(v));
}
__device__ __forceinline__ unsigned long long pk(float a, float b) {
    unsigned long long r;
    asm("mov.b64 %0, {%1, %2};" : "=l"(r) : "f"(a), "f"(b));
    return r;
}
__device__ __forceinline__ float sqapx(float x) {
    float r;
    asm("sqrt.approx.f32 %0, %1;" : "=f"(r) : "f"(x));
    return r;
}

// ---------------- Kernel 1: transpose + edge-record prep ----------------
__global__ void __launch_bounds__(256) transpose_kernel(
    const float2* __restrict__ in, const unsigned* __restrict__ skel_raw,
    const float* __restrict__ init_len, float* out, int N, int E, int tblocks) {
    if (blockIdx.x >= tblocks) {
        // ---- prep branch ----
        __shared__ int sh_is64;
        if (threadIdx.x < 32) {
            unsigned v = skel_raw[2 * threadIdx.x + 1] |
                         skel_raw[2 * (threadIdx.x + 32) + 1];
            unsigned b = __ballot_sync(0xffffffffu, v == 0u);
            if (threadIdx.x == 0) sh_is64 = (b == 0xffffffffu);
        }
        __syncthreads();
        int is64 = sh_is64;
        int e = (blockIdx.x - tblocks) * 256 + threadIdx.x;
        if (e == 0) out[0] = 0.0f;
        if (e < E_PAD) {
            uint4 r = make_uint4(0u, 0u, 0u, 0u);
            if (e < E) {
                int s0, s1;
                if (is64) {
                    longlong2 s = ((const longlong2*)skel_raw)[e];
                    s0 = (int)s.x; s1 = (int)s.y;
                } else {
                    int2 s = ((const int2*)skel_raw)[e];
                    s0 = s.x; s1 = s.y;
                }
                r.x = (unsigned)s0 * 256u;
                r.y = (unsigned)s1 * 256u;
                r.z = __float_as_uint(init_len[e]);
            }
            g_edges[e] = r;
        }
        return;
    }

    // ---- transpose branch ----
    __shared__ float2 tile[64][33];
    int n0 = blockIdx.x * 32;
    int tx = threadIdx.x & 31;
    int ty = threadIdx.x >> 5;
    int c = n0 + tx;
    if (c < N) {
#pragma unroll
        for (int i = 0; i < 8; ++i) {
            int b = ty + i * 8;  // frame index 0..63
            tile[b][tx] = __ldcs(&in[(size_t)b * N + c]);
        }
    }
    __syncthreads();
#pragma unroll
    for (int k = 0; k < 4; ++k) {
        int l = threadIdx.x + k * 256;
        int bp = l & 31;      // frame pair: frames 2bp, 2bp+1
        int cc = l >> 5;      // point within block
        int n = n0 + cc;
        if (n < N) {
            float2 v0 = tile[2 * bp][cc];
            float2 v1 = tile[2 * bp + 1][cc];
            char* base = (char*)g_buf + (size_t)n * 256 + (bp >> 1) * 16 + (bp & 1) * 4;
            *(__half2*)(base)     = __floats2half2_rn(v0.x, v1.x);  // x pair
            *(__half2*)(base + 8) = __floats2half2_rn(v0.y, v1.y);  // y pair
        }
    }
}

// ---------------- Kernel 2: main loss ----------------
// Warp = 4 edges (8 lanes each). Lane covers 8 frames via TWO uint4 chunks
// per endpoint (row halves at +0 and +128) => 4 gather LDG.128 + 1 record
// LDG.128 per warp-iter covering 256 (edge,frame) elements. Depth-2 register
// pipeline. Records pre-scaled; padded records contribute 0.

struct Rec { unsigned o0, o1; float c; };
struct GatherC { uint4 a0, a1, b0, b1; };  // 16 regs

__device__ __forceinline__ Rec load_rec(int e) {
    uint4 r = g_edges[e];
    Rec q;
    q.o0 = r.x;
    q.o1 = r.y;
    q.c = __uint_as_float(r.z);
    return q;
}

__device__ __forceinline__ GatherC issue_gather(const char* tb, Rec q) {
    GatherC g;
    g.a0 = *(const uint4*)(tb + q.o0);
    g.a1 = *(const uint4*)(tb + q.o0 + 128);
    g.b0 = *(const uint4*)(tb + q.o1);
    g.b1 = *(const uint4*)(tb + q.o1 + 128);
    return g;
}

__device__ __forceinline__ void body4(const uint4& A4, const uint4& B4,
                                      unsigned long long cc2,
                                      unsigned long long NEG1,
                                      unsigned long long& acc) {
    const __half2* A = (const __half2*)&A4;  // [x01, x23, y01, y23]
    const __half2* B = (const __half2*)&B4;
    __half2 dx01 = __hsub2(A[0], B[0]);
    __half2 dx23 = __hsub2(A[1], B[1]);
    __half2 dy01 = __hsub2(A[2], B[2]);
    __half2 dy23 = __hsub2(A[3], B[3]);
    __half2 t01 = __hfma2(dy01, dy01, __hmul2(dx01, dx01));
    __half2 t23 = __hfma2(dy23, dy23, __hmul2(dx23, dx23));
    float2 f01 = __half22float2(t01);
    float2 f23 = __half22float2(t23);
    unsigned long long len0 = pk(sqapx(f01.x), sqapx(f01.y));
    unsigned long long len1 = pk(sqapx(f23.x), sqapx(f23.y));
    unsigned long long d0 = fma2(cc2, NEG1, len0);
    unsigned long long d1 = fma2(cc2, NEG1, len1);
    acc = fma2(d0, d0, acc);
    acc = fma2(d1, d1, acc);
}

__global__ void __launch_bounds__(256, 5) loss_kernel(
    float* out, int E, float invE) {
    const unsigned long long NEG1 = 0xBF800000BF800000ULL;  // (-1.f, -1.f)
    int lane = threadIdx.x & 31;
    int quarter = lane >> 3;   // which of 4 edges in warp
    int el = lane & 7;         // chunk slot; covers chunks el and el+8
    int warp = (blockIdx.x * blockDim.x + threadIdx.x) >> 5;
    int nwarps = (gridDim.x * blockDim.x) >> 5;
    int P = (E + 3) >> 2;
    const char* tb = (const char*)g_buf + (unsigned)el * 16u;

    unsigned long long acc = 0ull;

    // Depth-2 prologue.
    int p = warp;
    Rec qc = load_rec(4 * p + quarter);
    GatherC gc = issue_gather(tb, qc);
    Rec qn = load_rec(4 * (p + nwarps) + quarter);

#pragma unroll 2
    for (; p < P; p += nwarps) {
        GatherC gn = issue_gather(tb, qn);
        Rec qf = load_rec(4 * (p + 2 * nwarps) + quarter);

        unsigned long long cc2 = pk(qc.c, qc.c);
        body4(gc.a0, gc.b0, cc2, NEG1, acc);
        body4(gc.a1, gc.b1, cc2, NEG1, acc);

        qc = qn;
        qn = qf;
        gc = gn;
    }

    float a0, a1;
    upk(acc, a0, a1);
    float s = a0 + a1;
#pragma unroll
    for (int off = 16; off; off >>= 1)
        s += __shfl_down_sync(0xffffffffu, s, off);

    __shared__ float warp_sums[8];
    if (lane == 0) warp_sums[threadIdx.x >> 5] = s;
    __syncthreads();
    if (threadIdx.x < 8) {
        float v = warp_sums[threadIdx.x];
#pragma unroll
        for (int off = 4; off; off >>= 1)
            v += __shfl_down_sync(0xffu, v, off);
        if (threadIdx.x == 0) atomicAdd(out, v * invE);
    }
}

extern "C" void kernel_launch(void* const* d_in, const int* in_sizes, int n_in,
                              void* d_out, int out_size) {
    const float2* pts = (const float2*)d_in[0];
    const void* skel = d_in[1];
    const float* initl = (const float*)d_in[2];
    float* out = (float*)d_out;

    int N = in_sizes[0] / 128;  // B=64 frames, 2 coords
    int E = in_sizes[2];

    int tblocks = (N + 31) / 32;
    int pblocks = (E_PAD + 255) / 256;
    transpose_kernel<<<tblocks + pblocks, 256>>>(
        pts, (const unsigned*)skel, initl, out, N, E, tblocks);
    loss_kernel<<<740, 256>>>(out, E, 1.0f / (float)E);
}